// round 17
// baseline (speedup 1.0000x reference)
#include <cuda_runtime.h>
#include <cuda_fp16.h>
#include <math.h>
#include <stdint.h>

#define Bb   8
#define Nn   2048
#define FIN  256
#define FOUT 128
#define CH   64          // attn j-chunk (128-byte fp16 rows)
#define NCH  (Nn / CH)   // 32
#define NTILES 256       // attn tiles: 8 batches x 32 i-tiles

typedef unsigned long long u64;
typedef unsigned int u32;

// Scratch (device globals: allocation-free rule)
__device__ __half g_WhT[Bb * FOUT * Nn];   // [b][f][j], fp16
__device__ __half g_Wt16[FOUT * FIN];      // [f][k], fp16 W^T
__device__ float  g_va1[FIN];              // W @ a1
__device__ float  g_va2[FIN];              // W @ a2
__device__ float  g_Ei[Bb * Nn];           // exp(f1) per i-node
__device__ float  g_Ej[Bb * Nn];           // exp(f2) per j-node
__device__ int    g_maxE2i[Bb];            // per-batch max of g_Ej (float bits)
__device__ int    g_tile_ctr;              // persistent-attn work counter

// ---------------- helpers ----------------
__forceinline__ __device__ u32 pkh2(float lo, float hi) {   // lo -> low half
    u32 r; asm("cvt.rn.f16x2.f32 %0,%1,%2;" : "=r"(r) : "f"(hi), "f"(lo)); return r;
}
__forceinline__ __device__ u32 smem_u32(const void* p) {
    u32 a;
    asm("{ .reg .u64 t; cvta.to.shared.u64 t,%1; cvt.u32.u64 %0,t; }" : "=r"(a) : "l"(p));
    return a;
}
__forceinline__ __device__ void mma16816(float* d, const u32* a, const u32* b) {
    asm volatile(
        "mma.sync.aligned.m16n8k16.row.col.f32.f16.f16.f32 "
        "{%0,%1,%2,%3},{%4,%5,%6,%7},{%8,%9},{%0,%1,%2,%3};"
        : "+f"(d[0]), "+f"(d[1]), "+f"(d[2]), "+f"(d[3])
        : "r"(a[0]), "r"(a[1]), "r"(a[2]), "r"(a[3]), "r"(b[0]), "r"(b[1]));
}
__forceinline__ __device__ void ldmx4(u32* d, u32 addr) {
    asm volatile("ldmatrix.sync.aligned.m8n8.x4.shared.b16 {%0,%1,%2,%3},[%4];"
        : "=r"(d[0]), "=r"(d[1]), "=r"(d[2]), "=r"(d[3]) : "r"(addr));
}
#define CP_ASYNC16(sdst, gsrc) \
    asm volatile("cp.async.cg.shared.global [%0], [%1], 16;" :: "r"(sdst), "l"(gsrc))
#define CP_COMMIT()  asm volatile("cp.async.commit_group;" ::: "memory")
#define CP_WAIT0()   asm volatile("cp.async.wait_group 0;" ::: "memory")

// ============================================================
// Kernel 0: prep — coalesced W transpose + va1/va2; resets tile ctr.
// ============================================================
__global__ __launch_bounds__(256) void gat_prep(
    const float* __restrict__ W, const float* __restrict__ a)
{
    __shared__ __align__(16) float ws[8][132];   // 528B rows: 16B-aligned
    __shared__ float as[2 * FOUT];
    const int t  = threadIdx.x;
    const int k0 = blockIdx.x * 8;

    if (blockIdx.x == 0 && t == 0) g_tile_ctr = 0;   // reset work queue

    as[t] = a[t];
    {
        int flat = t * 4;                 // 0..1023
        int kr   = flat >> 7;             // 0..7
        int f    = flat & 127;
        *(float4*)&ws[kr][f] = *(const float4*)&W[(size_t)(k0 + kr) * FOUT + f];
    }
    __syncthreads();

    // va1/va2: one warp per k-row (kr = t>>5), 4 f's per lane
    {
        const int kr = t >> 5;
        const int f0 = (t & 31) * 4;
        float s1 = 0.f, s2 = 0.f;
        #pragma unroll
        for (int u = 0; u < 4; u++) {
            float w = ws[kr][f0 + u];
            s1 += w * as[f0 + u];
            s2 += w * as[FOUT + f0 + u];
        }
        #pragma unroll
        for (int o = 16; o > 0; o >>= 1) {
            s1 += __shfl_xor_sync(0xffffffffu, s1, o);
            s2 += __shfl_xor_sync(0xffffffffu, s2, o);
        }
        if ((t & 31) == 0) { g_va1[k0 + kr] = s1; g_va2[k0 + kr] = s2; }
    }

    // Wt16 write: thread -> f = t>>1, 4 k's at kh (8 B store)
    {
        const int f  = t >> 1;
        const int kh = (t & 1) * 4;
        uint2 hb;
        hb.x = pkh2(ws[kh + 0][f], ws[kh + 1][f]);
        hb.y = pkh2(ws[kh + 2][f], ws[kh + 3][f]);
        *(uint2*)(g_Wt16 + (size_t)f * FIN + k0 + kh) = hb;
    }
}

// ============================================================
// Kernel 1: fused Wh = x@W (fp16 MMA) + f1/f2 (fp32) + exp + maxE2.
// (unchanged from R16-passing version)
// ============================================================
#define K1_A   0            // 2 x 64 rows x 128 B  = 16384
#define K1_B   16384        // 2 x 128 rows x 128 B = 32768
#define K1_VA  49152        // 2 x 256 floats       = 2048
#define K1_TOT 51200

__global__ __launch_bounds__(256, 2) void gat_gemm_wh(const float* __restrict__ x)
{
    extern __shared__ __align__(16) char dsm[];
    const u32 sb = smem_u32(dsm);
    float* va1s = (float*)(dsm + K1_VA);
    float* va2s = (float*)(dsm + K1_VA + 1024);

    const int t    = threadIdx.x;
    const int lane = t & 31;
    const int wid  = t >> 5;
    const int wr   = wid & 1;
    const int wc   = wid >> 1;
    const int g    = lane >> 2;
    const int cl   = lane & 3;
    const int sel  = lane >> 3, rin = lane & 7;
    const int b    = blockIdx.y;
    const int i0   = blockIdx.x * 64;

    va1s[t] = g_va1[t];
    va2s[t] = g_va2[t];

    u32 a_off[2][4], b_off[4][2];
    #pragma unroll
    for (int mt = 0; mt < 2; mt++)
        #pragma unroll
        for (int ks = 0; ks < 4; ks++) {
            int r = wr * 32 + mt * 16 + ((sel & 1) << 3) + rin;
            int c = ks * 2 + (sel >> 1);
            a_off[mt][ks] = (u32)(r * 128 + ((u32)(c ^ (r & 7)) << 4));
        }
    #pragma unroll
    for (int nt = 0; nt < 4; nt++)
        #pragma unroll
        for (int kb = 0; kb < 2; kb++) {
            int rr = wc * 32 + nt * 8 + rin;
            int c  = kb * 4 + sel;
            b_off[nt][kb] = (u32)(rr * 128 + ((u32)(c ^ (rr & 7)) << 4));
        }

    const int row  = t >> 2;
    const int kseg = (t & 3) * 16;
    const float* xb = x + ((size_t)b * Nn + i0 + row) * FIN + kseg;

    float acc[2][4][4];
    #pragma unroll
    for (int mt = 0; mt < 2; mt++)
        #pragma unroll
        for (int nt = 0; nt < 4; nt++)
            #pragma unroll
            for (int e = 0; e < 4; e++) acc[mt][nt][e] = 0.f;

    float4 xr[4];
    float  f1p = 0.f, f2p = 0.f;

    #define LDX(c_) do {                                                   \
        const float* _p = xb + (c_) * 64;                                  \
        xr[0] = *(const float4*)(_p);                                      \
        xr[1] = *(const float4*)(_p + 4);                                  \
        xr[2] = *(const float4*)(_p + 8);                                  \
        xr[3] = *(const float4*)(_p + 12);                                 \
    } while (0)

    #define BUILD_A(c_, buf_) do {                                         \
        const int _kb = (c_) * 64 + kseg;                                  \
        _Pragma("unroll")                                                  \
        for (int q = 0; q < 4; q++) {                                      \
            float4 v1 = *(const float4*)&va1s[_kb + q * 4];                \
            float4 v2 = *(const float4*)&va2s[_kb + q * 4];                \
            f1p += xr[q].x*v1.x + xr[q].y*v1.y + xr[q].z*v1.z + xr[q].w*v1.w; \
            f2p += xr[q].x*v2.x + xr[q].y*v2.y + xr[q].z*v2.z + xr[q].w*v2.w; \
        }                                                                   \
        uint4 h0, h1;                                                       \
        h0.x = pkh2(xr[0].x, xr[0].y); h0.y = pkh2(xr[0].z, xr[0].w);      \
        h0.z = pkh2(xr[1].x, xr[1].y); h0.w = pkh2(xr[1].z, xr[1].w);      \
        h1.x = pkh2(xr[2].x, xr[2].y); h1.y = pkh2(xr[2].z, xr[2].w);      \
        h1.z = pkh2(xr[3].x, xr[3].y); h1.w = pkh2(xr[3].z, xr[3].w);      \
        u32 jc = (u32)((t & 3) * 2);                                        \
        *(uint4*)(dsm + K1_A + (buf_) * 8192 + row * 128                    \
                  + ((jc ^ (u32)(row & 7)) << 4)) = h0;                     \
        *(uint4*)(dsm + K1_A + (buf_) * 8192 + row * 128                    \
                  + (((jc + 1) ^ (u32)(row & 7)) << 4)) = h1;               \
    } while (0)

    #define ISSUE_B(c_, buf_) do {                                         \
        const int _k0 = (c_) * 64;                                         \
        const u32 _bb = sb + K1_B + (buf_) * 16384;                        \
        _Pragma("unroll")                                                  \
        for (int q = 0; q < 4; q++) {                                      \
            int flat = t + 256 * q;                                        \
            int frow = flat >> 3;                                          \
            int jc2  = flat & 7;                                           \
            u32 sidx = (u32)(frow * 128 + (((u32)(jc2 ^ (frow & 7))) << 4)); \
            CP_ASYNC16(_bb + sidx,                                         \
                       g_Wt16 + (size_t)frow * FIN + _k0 + jc2 * 8);       \
        }                                                                   \
        CP_COMMIT();                                                        \
    } while (0)

    LDX(0);
    ISSUE_B(0, 0);
    __syncthreads();                    // va1s/va2s visible
    BUILD_A(0, 0);
    CP_WAIT0();
    __syncthreads();

    for (int c = 0; c < 4; c++) {
        const int s = c & 1;
        if (c < 3) { LDX(c + 1); ISSUE_B(c + 1, s ^ 1); }

        const u32 ab = sb + K1_A + s * 8192;
        const u32 bb = sb + K1_B + s * 16384;
        #pragma unroll
        for (int kb = 0; kb < 2; kb++) {
            u32 bfr[4][4];
            #pragma unroll
            for (int nt = 0; nt < 4; nt++)
                ldmx4(bfr[nt], bb + b_off[nt][kb]);
            #pragma unroll
            for (int h = 0; h < 2; h++) {
                u32 afr[2][4];
                ldmx4(afr[0], ab + a_off[0][kb * 2 + h]);
                ldmx4(afr[1], ab + a_off[1][kb * 2 + h]);
                #pragma unroll
                for (int nt = 0; nt < 4; nt++) {
                    mma16816(acc[0][nt], afr[0], &bfr[nt][h * 2]);
                    mma16816(acc[1][nt], afr[1], &bfr[nt][h * 2]);
                }
            }
        }

        if (c < 3) BUILD_A(c + 1, s ^ 1);
        CP_WAIT0();
        __syncthreads();
    }

    f1p += __shfl_xor_sync(0xffffffffu, f1p, 1);
    f1p += __shfl_xor_sync(0xffffffffu, f1p, 2);
    f2p += __shfl_xor_sync(0xffffffffu, f2p, 1);
    f2p += __shfl_xor_sync(0xffffffffu, f2p, 2);
    float E2 = 0.f;
    if ((t & 3) == 0) {
        size_t R = (size_t)b * Nn + i0 + row;
        float E1 = __expf(f1p);
        E2 = __expf(f2p);
        g_Ei[R] = E1;
        g_Ej[R] = E2;
    }
    float wm = E2;
    #pragma unroll
    for (int o = 16; o > 0; o >>= 1)
        wm = fmaxf(wm, __shfl_xor_sync(0xffffffffu, wm, o));
    if (lane == 0) atomicMax(&g_maxE2i[b], __float_as_int(wm));

    __half* tr = (__half*)dsm;
    #pragma unroll
    for (int mt = 0; mt < 2; mt++)
        #pragma unroll
        for (int nt = 0; nt < 4; nt++)
            #pragma unroll
            for (int h = 0; h < 2; h++)
                #pragma unroll
                for (int e = 0; e < 2; e++) {
                    int f = wc * 32 + nt * 8 + cl * 2 + e;
                    int j = wr * 32 + mt * 16 + g + 8 * h;
                    tr[(size_t)f * 72 + j] = __float2half(acc[mt][nt][h * 2 + e]);
                }
    __syncthreads();

    {
        const int f   = t >> 1;
        const int seg = (t & 1) * 32;
        const __half* trow = tr + (size_t)f * 72 + seg;
        __half* dst = g_WhT + ((size_t)(b * FOUT + f)) * Nn + i0 + seg;
        #pragma unroll
        for (int m = 0; m < 4; m++)
            *(uint4*)(dst + m * 8) = *(const uint4*)(trow + m * 8);
    }
}

// ============================================================
// Kernel 2: fused attention — persistent work-stealing wrapper
// around the R16-passing tile body. Grid 296 (= 148 SMs x occ 2);
// tiles fetched via atomicAdd for perfect load balance.
// ============================================================
#define SM_PS   0                        // 2 * 64*128B  = 16384
#define SM_WS   16384                    // 2 * 128*128B = 32768
#define SM_RS   49152                    // 64 floats
#define SM_TOT  49408

__global__ __launch_bounds__(256, 2) void gat_attn(
    const int* __restrict__ adj, float* __restrict__ out)
{
    extern __shared__ __align__(16) char dsm[];
    float* rows = (float*)(dsm + SM_RS);
    __shared__ int s_tile;
    const u32 sb = smem_u32(dsm);

    const int t    = threadIdx.x;
    const int lane = t & 31;
    const int wid  = t >> 5;
    const int wr   = wid & 1;
    const int wc   = wid >> 1;
    const int g    = lane >> 2;
    const int cl   = lane & 3;

    const int sel = lane >> 3, rin = lane & 7;
    u32 a_off[2][4], b_off[4][2];
    #pragma unroll
    for (int mt = 0; mt < 2; mt++)
        #pragma unroll
        for (int ks = 0; ks < 4; ks++) {
            int r = wr * 32 + mt * 16 + ((sel & 1) << 3) + rin;
            int c = ks * 2 + (sel >> 1);
            a_off[mt][ks] = (u32)(r * 128 + ((u32)(c ^ (r & 7)) << 4));
        }
    #pragma unroll
    for (int nt = 0; nt < 4; nt++)
        #pragma unroll
        for (int kb = 0; kb < 2; kb++) {
            int rr = wc * 32 + nt * 8 + rin;
            int c  = kb * 4 + sel;
            b_off[nt][kb] = (u32)(rr * 128 + ((u32)(c ^ (rr & 7)) << 4));
        }

    const int iL = t >> 2;
    const int jq = t & 3;
    const int jh = jq * 16;
    u32 pst[2];
    #pragma unroll
    for (int q = 0; q < 2; q++)
        pst[q] = (u32)(iL * 128 + (((u32)((jq * 2 + q) ^ (iL & 7))) << 4));

    for (;;) {
        if (t == 0) s_tile = atomicAdd(&g_tile_ctr, 1);
        __syncthreads();
        const int tile = s_tile;
        if (tile >= NTILES) break;
        const int b  = tile >> 5;
        const int i0 = (tile & 31) * 64;

        const float c1  = g_Ei[(size_t)b * Nn + i0 + iL];
        const float mE2 = __int_as_float(g_maxE2i[b]);
        const float thrE = 1.0f / c1;
        float pm = c1 * mE2;
        pm = (pm >= 1.f) ? pm : pm * pm;
        int ex = (int)((__float_as_uint(pm) >> 23) & 255u) - 127;
        int kk = ex - 11; if (kk < 0) kk = 0;
        const float scale = __uint_as_float((u32)(127 - kk) << 23);
        const float c1s = c1 * scale;
        const float c2s = c1 * c1 * scale;

        const int*    arow = adj  + ((size_t)(b * Nn + i0 + iL)) * Nn + jh;
        const float*  Ejb  = g_Ej + (size_t)b * Nn + jh;
        const __half* whtb = g_WhT + (size_t)b * FOUT * Nn;

        float acc[2][4][4];
        #pragma unroll
        for (int mt = 0; mt < 2; mt++)
            #pragma unroll
            for (int nt = 0; nt < 4; nt++)
                #pragma unroll
                for (int e = 0; e < 4; e++) acc[mt][nt][e] = 0.f;

        int4   sav[4];
        float4 sev[4];
        float  rs = 0.f;

        #define ISSUE_G(c_) do {                                              \
            const int _j0 = (c_) * CH;                                        \
            _Pragma("unroll")                                                 \
            for (int q = 0; q < 4; q++) {                                     \
                sav[q] = *(const int4*)&arow[_j0 + q * 4];                    \
                sev[q] = *(const float4*)&Ejb[_j0 + q * 4];                   \
            }                                                                  \
        } while (0)

        #define ISSUE_W(c_, buf_) do {                                        \
            const int _j0 = (c_) * CH;                                        \
            const u32 _wb = sb + SM_WS + (buf_) * 16384;                      \
            _Pragma("unroll")                                                 \
            for (int q = 0; q < 4; q++) {                                     \
                int flat = t + 256 * q;                                       \
                int row  = flat >> 3;                                         \
                int jc   = flat & 7;                                          \
                u32 sidx = (u32)(row * 128 + (((u32)(jc ^ (row & 7))) << 4)); \
                CP_ASYNC16(_wb + sidx,                                        \
                           &whtb[(size_t)row * Nn + _j0 + jc * 8]);           \
            }                                                                  \
            CP_COMMIT();                                                       \
        } while (0)

        #define FINISH(buf_) do {                                              \
            const int*   _a = (const int*)sav;                                 \
            const float* _e = (const float*)sev;                               \
            _Pragma("unroll")                                                   \
            for (int q = 0; q < 2; q++) {                                       \
                uint4 pv; u32* pw = (u32*)&pv;                                  \
                _Pragma("unroll")                                               \
                for (int u = 0; u < 4; u++) {                                   \
                    int i2 = q * 8 + u * 2;                                     \
                    float E0 = _e[i2], E1 = _e[i2 + 1];                         \
                    float m0 = (E0 >= thrE) ? c1s : c2s * E0;                   \
                    float m1 = (E1 >= thrE) ? c1s : c2s * E1;                   \
                    float p0 = (_a[i2]     > 0) ? m0 * E0 : 0.f;                \
                    float p1 = (_a[i2 + 1] > 0) ? m1 * E1 : 0.f;                \
                    pw[u] = pkh2(p0, p1);                                       \
                    rs += p0 + p1;                                              \
                }                                                                \
                *(uint4*)(dsm + SM_PS + (buf_) * 8192 + pst[q]) = pv;           \
            }                                                                    \
        } while (0)

        ISSUE_W(0, 0);
        ISSUE_G(0);
        FINISH(0);
        CP_WAIT0();
        __syncthreads();

        for (int c = 0; c < NCH; c++) {
            const int s = c & 1;
            if (c < NCH - 1) { ISSUE_G(c + 1); ISSUE_W(c + 1, s ^ 1); }

            {
                const u32 pb = sb + SM_PS + s * 8192;
                const u32 wb = sb + SM_WS + s * 16384;
                #pragma unroll
                for (int kb = 0; kb < 2; kb++) {
                    u32 bfr[4][4];
                    #pragma unroll
                    for (int nt = 0; nt < 4; nt++)
                        ldmx4(bfr[nt], wb + b_off[nt][kb]);
                    #pragma unroll
                    for (int h = 0; h < 2; h++) {
                        u32 afr[2][4];
                        ldmx4(afr[0], pb + a_off[0][kb * 2 + h]);
                        ldmx4(afr[1], pb + a_off[1][kb * 2 + h]);
                        #pragma unroll
                        for (int nt = 0; nt < 4; nt++) {
                            mma16816(acc[0][nt], afr[0], &bfr[nt][h * 2]);
                            mma16816(acc[1][nt], afr[1], &bfr[nt][h * 2]);
                        }
                    }
                }
            }

            if (c < NCH - 1) FINISH(s ^ 1);
            CP_WAIT0();
            __syncthreads();
        }

        rs += __shfl_xor_sync(0xffffffffu, rs, 1);
        rs += __shfl_xor_sync(0xffffffffu, rs, 2);
        if ((t & 3) == 0) rows[iL] = rs;
        __syncthreads();

        #pragma unroll
        for (int mt = 0; mt < 2; mt++)
            #pragma unroll
            for (int h = 0; h < 2; h++) {
                const int row = wr * 32 + mt * 16 + g + h * 8;
                const float inv = 1.0f / rows[row];
                float* orow = out + ((size_t)(b * Nn + i0 + row)) * FOUT + wc * 32 + cl * 2;
                #pragma unroll
                for (int nt = 0; nt < 4; nt++) {
                    float h0 = acc[mt][nt][h * 2 + 0] * inv;
                    float h1 = acc[mt][nt][h * 2 + 1] * inv;
                    h0 = (h0 > 0.f) ? h0 : expm1f(h0);
                    h1 = (h1 > 0.f) ? h1 : expm1f(h1);
                    float2 o = make_float2(h0, h1);
                    *(float2*)&orow[nt * 8] = o;
                }
            }

        __syncthreads();   // isolate smem (rows/Ps/Ws) before next tile
    }
}

// ============================================================
extern "C" void kernel_launch(void* const* d_in, const int* in_sizes, int n_in,
                              void* d_out, int out_size)
{
    const float* x   = (const float*)d_in[0];   // [8,2048,256] f32
    const int*   adj = (const int*)  d_in[1];   // [8,2048,2048] i32
    const float* W   = (const float*)d_in[2];   // [256,128] f32
    const float* a   = (const float*)d_in[3];   // [256,1] f32
    float*       out = (float*)d_out;           // [8,2048,128] f32

    gat_prep<<<32, 256>>>(W, a);

    cudaFuncSetAttribute(gat_gemm_wh, cudaFuncAttributeMaxDynamicSharedMemorySize, K1_TOT);
    cudaFuncSetAttribute(gat_attn,    cudaFuncAttributeMaxDynamicSharedMemorySize, SM_TOT);

    dim3 g1(Nn / 64, Bb);
    gat_gemm_wh<<<g1, 256, K1_TOT>>>(x);

    gat_attn<<<296, 256, SM_TOT>>>(adj, out);
}